// round 14
// baseline (speedup 1.0000x reference)
#include <cuda_runtime.h>
#include <cuda_bf16.h>
#include <cstdint>

// Problem constants
#define SEQ    4096
#define DK     128
#define PLANE  (SEQ * DK)      // 524288 floats per (b,h) plane
#define PLANE4 (PLANE / 4)     // 131072 float4s per plane
#define PPB    4               // planes per block
#define STILE  64              // s-rows per block (2048 float4s per tile)

// out[...,s,d] = R[d,d,s] * x[...,s,d]  (einsum diagonal => elementwise scale)
// 512-thread blocks, 64-seq x 128-dim tile, PPB planes (2 pairs).
// Diag slice read straight from R (coalesced, L2-cached) into smem, cached
// in registers. .cs on loads+stores (read-once/write-once stream).
__global__ void __launch_bounds__(512) rope_diag_kernel(
        const float* __restrict__ R,
        const float4* __restrict__ x,
        float4* __restrict__ out) {
    // Padded to 132 floats/row: 16B-aligned rows -> conflict-free LDS.128
    __shared__ float diag[STILE][132];

    const unsigned s0     = blockIdx.x * STILE;     // 64 s-tiles (fast)
    const unsigned plane0 = blockIdx.y * PPB;       // 32 plane-quads
    const unsigned tid    = threadIdx.x;            // 0..511
    const unsigned warp   = tid >> 5;               // 0..15
    const unsigned lane   = tid & 31;

    // diag[s][d] = R[d*(DK+1)*SEQ + s]; each warp fills 32 s for 8 d values:
    // warp w covers d = w, w+16, ..., s-range split in halves by warp group.
    // Simpler: 16 warps x 8 rows each = 128 d-rows over 2 s-halves.
    #pragma unroll
    for (int r = 0; r < 16; r++) {
        unsigned d  = (warp & 7) + r * 8;           // 0..127
        unsigned sh = (warp >> 3) * 32;             // 0 or 32: s-half
        diag[sh + lane][d] =
            __ldg(&R[(size_t)d * ((DK + 1) * SEQ) + s0 + sh + lane]);
    }
    __syncthreads();

    const unsigned tileBase = blockIdx.x * (STILE * 32);  // float4 offset

    // Pre-read this thread's 4 diag chunks once (16 regs, reused x4 planes)
    float4 dvv[4];
    #pragma unroll
    for (int k = 0; k < 4; k++) {
        unsigned idx = k * 512 + tid;               // 0..2047 within tile
        unsigned s   = idx >> 5;                    // 0..63
        unsigned d4  = (idx & 31) * 4;              // 0..124
        dvv[k] = *reinterpret_cast<const float4*>(&diag[s][d4]);
    }

    // Process planes in pairs: 8 front-batched float4 loads per pair.
    #pragma unroll
    for (int pp = 0; pp < PPB / 2; pp++) {
        const unsigned pA = plane0 + pp * 2;

        float4 xv[2][4];
        #pragma unroll
        for (int p = 0; p < 2; p++) {
            const float4* xp = x + (size_t)(pA + p) * PLANE4 + tileBase;
            #pragma unroll
            for (int k = 0; k < 4; k++)
                xv[p][k] = __ldcs(&xp[k * 512 + tid]);
        }

        #pragma unroll
        for (int k = 0; k < 4; k++) {
            unsigned idx = k * 512 + tid;
            #pragma unroll
            for (int p = 0; p < 2; p++) {
                float4 r;
                r.x = xv[p][k].x * dvv[k].x;
                r.y = xv[p][k].y * dvv[k].y;
                r.z = xv[p][k].z * dvv[k].z;
                r.w = xv[p][k].w * dvv[k].w;
                __stcs(&out[(size_t)(pA + p) * PLANE4 + tileBase + idx], r);
            }
        }
    }
}

extern "C" void kernel_launch(void* const* d_in, const int* in_sizes, int n_in,
                              void* d_out, int out_size) {
    const float* x = (const float*)d_in[0];
    // d_in[1] = token_positions (unused by the reference semantics)
    const float* R = (const float*)d_in[2];
    float* out = (float*)d_out;

    dim3 grid(SEQ / STILE, 128 / PPB);   // (64, 32) = 2048 blocks
    rope_diag_kernel<<<grid, 512>>>(R, (const float4*)x, (float4*)out);
    (void)in_sizes; (void)n_in; (void)out_size;
}